// round 12
// baseline (speedup 1.0000x reference)
#include <cuda_runtime.h>
#include <cuda_fp16.h>
#include <math_constants.h>
#include <cstdint>

#define NROWS 8192
#define DDIM  512
#define MTILE 128
#define NTILE 128
#define BKH 64                            // halves per k-stage
#define NSTAGES (DDIM / BKH)              // 8
#define NBANDS (NROWS / NTILE)            // 64
#define SMS 72                            // smem row stride in halves (64 + 8 pad)
#define TILE_BYTES (MTILE * SMS * 2)      // 18432
#define DYN_SMEM (6 * TILE_BYTES)         // 3 stages x (A+B) = 110592

typedef unsigned long long u64;
#define KPOS_INIT 0xFFFFFFFFFFFFFFFFull
#define KNEG_INIT 0ull

// ---------------- scratch ----------------
__device__ __half g_unith[NROWS * DDIM];  // fp16 unit vectors (8 MB, L2-resident)
__device__ u64    g_posKey[NROWS];        // min over (ord(dot)<<32 | j)
__device__ u64    g_negKey[NROWS];        // max over (ord(dot)<<32 | (~0u - j))
__device__ u64    g_sumFix;               // sum(loss * 2^32), order-independent
__device__ unsigned int g_cnt;
__device__ unsigned int g_done;

// ---------------- helpers ----------------
__device__ __forceinline__ uint32_t smem_u32(const void* p) {
    uint32_t a;
    asm("{ .reg .u64 t; cvta.to.shared.u64 t, %1; cvt.u32.u64 %0, t; }"
        : "=r"(a) : "l"(p));
    return a;
}

__device__ __forceinline__ void cp16(uint32_t dst, const void* src) {
    asm volatile("cp.async.cg.shared.global [%0], [%1], 16;"
                 :: "r"(dst), "l"(src));
}
#define CP_COMMIT() asm volatile("cp.async.commit_group;" ::: "memory")
#define CP_WAIT(n)  asm volatile("cp.async.wait_group %0;" :: "n"(n) : "memory")

__device__ __forceinline__ void ldm_x4(uint32_t* r, uint32_t addr) {
    asm volatile("ldmatrix.sync.aligned.m8n8.x4.shared.b16 {%0,%1,%2,%3}, [%4];"
                 : "=r"(r[0]), "=r"(r[1]), "=r"(r[2]), "=r"(r[3]) : "r"(addr));
}

// monotonic float -> uint mapping
__device__ __forceinline__ uint32_t ford(float f) {
    uint32_t u = __float_as_uint(f);
    return u ^ (uint32_t)(((int32_t)u >> 31) | 0x80000000);
}

__device__ __forceinline__ void mma_f16(float* c, const uint32_t* a,
                                        uint32_t b0, uint32_t b1) {
    asm volatile(
        "mma.sync.aligned.m16n8k16.row.col.f32.f16.f16.f32 "
        "{%0,%1,%2,%3}, {%4,%5,%6,%7}, {%8,%9}, {%0,%1,%2,%3};"
        : "+f"(c[0]), "+f"(c[1]), "+f"(c[2]), "+f"(c[3])
        : "r"(a[0]), "r"(a[1]), "r"(a[2]), "r"(a[3]), "r"(b0), "r"(b1));
}

// ---------------- kernel 1: normalize (warp per row, no barriers) ------------
__global__ void normalize_kernel(const float* __restrict__ emb) {
    int gw   = (blockIdx.x * blockDim.x + threadIdx.x) >> 5;   // row
    int lane = threadIdx.x & 31;
    if (gw >= NROWS) return;

    const float4* src = (const float4*)(emb + (size_t)gw * DDIM);
    float4 v[4];
    float s = 0.0f;
    #pragma unroll
    for (int i = 0; i < 4; i++) {
        v[i] = src[lane + 32 * i];
        s += v[i].x * v[i].x + v[i].y * v[i].y + v[i].z * v[i].z + v[i].w * v[i].w;
    }
    #pragma unroll
    for (int o = 16; o; o >>= 1) s += __shfl_xor_sync(0xffffffffu, s, o);
    float inv = 1.0f / fmaxf(sqrtf(s), 1e-8f);

    __half2* dst = (__half2*)(g_unith + (size_t)gw * DDIM);
    #pragma unroll
    for (int i = 0; i < 4; i++) {
        dst[(lane + 32 * i) * 2]     = __floats2half2_rn(v[i].x * inv, v[i].y * inv);
        dst[(lane + 32 * i) * 2 + 1] = __floats2half2_rn(v[i].z * inv, v[i].w * inv);
    }
    if (lane == 0) {
        g_posKey[gw] = KPOS_INIT;
        g_negKey[gw] = KNEG_INIT;
    }
    if (gw == 0 && lane == 0) { g_sumFix = 0ull; g_cnt = 0u; g_done = 0u; }
}

// ---------------- kernel 2: fp16 mma Gram, one 128x128 tile per CTA ----------
// grid (33, 64): bi = blockIdx.y, bj = (bi + d) % 64, d = blockIdx.x.
// Upper-triangle coverage; d==32 duplicates for bi>=32 are skipped.
// 3-stage cp.async pipeline (K=64/stage), register-double-buffered fragments.
__global__ void __launch_bounds__(256)
mine_kernel(const int* __restrict__ labels) {
    extern __shared__ __half dyn[];
    __shared__ u64 rowPos[128], rowNeg[128], colPos[128], colNeg[128];
    __shared__ int lblI[128], lblJ[128];

    const int d  = blockIdx.x;
    const int bi = blockIdx.y;
    if (d == 32 && bi >= 32) return;
    const int bj = (bi + d) & (NBANDS - 1);
    const int i0 = bi * MTILE;
    const int j0 = bj * NTILE;

    const int tid  = threadIdx.x;
    const int lane = tid & 31;
    const int wid  = tid >> 5;
    const int gid  = lane >> 2;     // 0..7
    const int tig  = lane & 3;      // 0..3
    const int wr   = wid >> 1;      // 0..3 (row band: wr*32)
    const int wc   = wid & 1;       // 0..1 (col band: wc*64)

    if (tid < 128) {
        lblI[tid] = labels[i0 + tid];
        lblJ[tid] = labels[j0 + tid];
        rowPos[tid] = KPOS_INIT; rowNeg[tid] = KNEG_INIT;
        colPos[tid] = KPOS_INIT; colNeg[tid] = KNEG_INIT;
    }
    __syncthreads();

    int myLbl[2][2];
    #pragma unroll
    for (int mi = 0; mi < 2; mi++)
        #pragma unroll
        for (int h = 0; h < 2; h++)
            myLbl[mi][h] = lblI[wr * 32 + mi * 16 + h * 8 + gid];

    const uint32_t sbase = smem_u32(dyn);
    uint32_t abuf[3], bbuf[3];
    #pragma unroll
    for (int s = 0; s < 3; s++) {
        abuf[s] = sbase + s * TILE_BYTES;
        bbuf[s] = sbase + (3 + s) * TILE_BYTES;
    }

    // per-thread cp.async offsets: 256 threads = 32 rows x 8 cols of 16B
    const int ldrow = tid >> 3;               // 0..31 (x4 iters -> 128 rows)
    const int ldc   = tid & 7;                // 0..7
    uint32_t soff[4];
    #pragma unroll
    for (int it = 0; it < 4; it++)
        soff[it] = (uint32_t)((ldrow + it * 32) * SMS + ldc * 8) * 2u;

    // ldmatrix lane address bases (in halves)
    const int lr = lane & 7;
    const int rowA = wr * 32 + ((lane >> 3) & 1) * 8 + lr;  // + mi*16
    const int kA   = (lane >> 4) * 8;                        // + kk*16
    const int nB   = wc * 64 + (lane >> 4) * 8 + lr;         // + ni2*16
    const int kB   = ((lane >> 3) & 1) * 8;                  // + kk*16

    float acc[2][8][4];
    #pragma unroll
    for (int mi = 0; mi < 2; mi++)
        #pragma unroll
        for (int ni = 0; ni < 8; ni++)
            #pragma unroll
            for (int q = 0; q < 4; q++) acc[mi][ni][q] = 0.0f;

    // ---- prologue: commit stages 0 and 1 ----
    #pragma unroll
    for (int s = 0; s < 2; s++) {
        const int k0 = s * BKH;
        #pragma unroll
        for (int it = 0; it < 4; it++) {
            cp16(abuf[s] + soff[it], g_unith + (size_t)(i0 + ldrow + it * 32) * DDIM + k0 + ldc * 8);
            cp16(bbuf[s] + soff[it], g_unith + (size_t)(j0 + ldrow + it * 32) * DDIM + k0 + ldc * 8);
        }
        CP_COMMIT();
    }

    int buf = 0;
    for (int s = 0; s < NSTAGES; s++) {
        CP_WAIT(1);
        __syncthreads();   // publish stage s; all warps done reading buf of s-1

        if (s + 2 < NSTAGES) {
            const int nb = (buf + 2 >= 3) ? buf - 1 : buf + 2;
            const int k0 = (s + 2) * BKH;
            #pragma unroll
            for (int it = 0; it < 4; it++) {
                cp16(abuf[nb] + soff[it], g_unith + (size_t)(i0 + ldrow + it * 32) * DDIM + k0 + ldc * 8);
                cp16(bbuf[nb] + soff[it], g_unith + (size_t)(j0 + ldrow + it * 32) * DDIM + k0 + ldc * 8);
            }
            CP_COMMIT();
        } else {
            CP_COMMIT();   // keep group count in lockstep for CP_WAIT(1)
        }

        const uint32_t abase = abuf[buf];
        const uint32_t bbase = bbuf[buf];

        // register-double-buffered fragments: prefetch kk+1 while computing kk
        uint32_t fa0[2][4], fa1[2][4], fb[2][16];
        ldm_x4(fa0[0], abase + (uint32_t)((rowA)      * SMS + kA) * 2u);
        ldm_x4(fa1[0], abase + (uint32_t)((rowA + 16) * SMS + kA) * 2u);
        #pragma unroll
        for (int ni2 = 0; ni2 < 4; ni2++)
            ldm_x4(&fb[0][ni2 * 4], bbase + (uint32_t)((nB + ni2 * 16) * SMS + kB) * 2u);

        #pragma unroll
        for (int kk = 0; kk < 4; kk++) {
            const int cur = kk & 1, nxt = cur ^ 1;
            if (kk < 3) {
                const int ko = (kk + 1) * 16;
                ldm_x4(fa0[nxt], abase + (uint32_t)((rowA)      * SMS + kA + ko) * 2u);
                ldm_x4(fa1[nxt], abase + (uint32_t)((rowA + 16) * SMS + kA + ko) * 2u);
                #pragma unroll
                for (int ni2 = 0; ni2 < 4; ni2++)
                    ldm_x4(&fb[nxt][ni2 * 4], bbase + (uint32_t)((nB + ni2 * 16) * SMS + kB + ko) * 2u);
            }
            #pragma unroll
            for (int ni2 = 0; ni2 < 4; ni2++) {
                mma_f16(acc[0][2 * ni2],     fa0[cur], fb[cur][4 * ni2],     fb[cur][4 * ni2 + 1]);
                mma_f16(acc[0][2 * ni2 + 1], fa0[cur], fb[cur][4 * ni2 + 2], fb[cur][4 * ni2 + 3]);
                mma_f16(acc[1][2 * ni2],     fa1[cur], fb[cur][4 * ni2],     fb[cur][4 * ni2 + 1]);
                mma_f16(acc[1][2 * ni2 + 1], fa1[cur], fb[cur][4 * ni2 + 2], fb[cur][4 * ni2 + 3]);
            }
        }
        buf = (buf + 1 >= 3) ? 0 : buf + 1;
    }

    // ---- row-side selection (rows of band bi) ----
    #pragma unroll
    for (int mi = 0; mi < 2; mi++) {
        #pragma unroll
        for (int h = 0; h < 2; h++) {
            int r   = wr * 32 + mi * 16 + h * 8 + gid;
            int gi  = i0 + r;
            int lbl = myLbl[mi][h];
            u64 pk = KPOS_INIT, nk = KNEG_INIT;
            #pragma unroll
            for (int ni = 0; ni < 8; ni++) {
                #pragma unroll
                for (int u = 0; u < 2; u++) {
                    int jc = wc * 64 + ni * 8 + tig * 2 + u;
                    int j  = j0 + jc;
                    u64 od = (u64)ford(acc[mi][ni][h * 2 + u]) << 32;
                    if (lblJ[jc] == lbl) {
                        if (j != gi) {
                            u64 k = od | (uint32_t)j;
                            if (k < pk) pk = k;
                        }
                    } else {
                        u64 k = od | (uint32_t)(0xFFFFFFFFu - j);
                        if (k > nk) nk = k;
                    }
                }
            }
            #pragma unroll
            for (int off = 2; off; off >>= 1) {
                u64 opk = __shfl_down_sync(0xffffffffu, pk, off, 4);
                u64 onk = __shfl_down_sync(0xffffffffu, nk, off, 4);
                if (opk < pk) pk = opk;
                if (onk > nk) nk = onk;
            }
            if (tig == 0) {
                if (pk != KPOS_INIT) atomicMin(&rowPos[r], pk);
                if (nk != KNEG_INIT) atomicMax(&rowNeg[r], nk);
            }
        }
    }

    // ---- column-side selection (rows of band bj, via transpose) ----
    #pragma unroll
    for (int ni = 0; ni < 8; ni++) {
        #pragma unroll
        for (int u = 0; u < 2; u++) {
            int jc = wc * 64 + ni * 8 + tig * 2 + u;
            int gj = j0 + jc;
            int lj = lblJ[jc];
            u64 pk = KPOS_INIT, nk = KNEG_INIT;
            #pragma unroll
            for (int mi = 0; mi < 2; mi++) {
                #pragma unroll
                for (int h = 0; h < 2; h++) {
                    int gi = i0 + wr * 32 + mi * 16 + h * 8 + gid;
                    u64 od = (u64)ford(acc[mi][ni][h * 2 + u]) << 32;
                    if (myLbl[mi][h] == lj) {
                        if (gi != gj) {
                            u64 k = od | (uint32_t)gi;
                            if (k < pk) pk = k;
                        }
                    } else {
                        u64 k = od | (uint32_t)(0xFFFFFFFFu - gi);
                        if (k > nk) nk = k;
                    }
                }
            }
            #pragma unroll
            for (int off = 16; off >= 4; off >>= 1) {
                u64 opk = __shfl_down_sync(0xffffffffu, pk, off);
                u64 onk = __shfl_down_sync(0xffffffffu, nk, off);
                if (opk < pk) pk = opk;
                if (onk > nk) nk = onk;
            }
            if (gid == 0) {
                if (pk != KPOS_INIT) atomicMin(&colPos[jc], pk);
                if (nk != KNEG_INIT) atomicMax(&colNeg[jc], nk);
            }
        }
    }
    __syncthreads();

    // ---- flush both bands (min/max idempotent -> diagonal overlap is safe) ----
    if (tid < 128) {
        u64 rp = rowPos[tid], rn = rowNeg[tid];
        u64 cp = colPos[tid], cn = colNeg[tid];
        if (rp != KPOS_INIT) atomicMin(&g_posKey[i0 + tid], rp);
        if (rn != KNEG_INIT) atomicMax(&g_negKey[i0 + tid], rn);
        if (cp != KPOS_INIT) atomicMin(&g_posKey[j0 + tid], cp);
        if (cn != KNEG_INIT) atomicMax(&g_negKey[j0 + tid], cn);
    }
}

// ---------------- kernel 3: triplet loss (warp per row) + fused reduction ----
__global__ void triplet_kernel(const float* __restrict__ emb, float* __restrict__ out) {
    __shared__ u64 ssum;
    __shared__ unsigned int scnt;
    int tid  = threadIdx.x;
    int lane = tid & 31;
    int i    = blockIdx.x * 8 + (tid >> 5);     // row handled by this warp

    if (tid == 0) { ssum = 0ull; scnt = 0u; }
    __syncthreads();

    u64 pk = g_posKey[i];
    u64 nk = g_negKey[i];
    bool valid = (pk != KPOS_INIT) && (nk != KNEG_INIT);
    if (valid) {
        int pi = (int)(uint32_t)(pk & 0xFFFFFFFFull);
        int ni = (int)(0xFFFFFFFFu - (uint32_t)(nk & 0xFFFFFFFFull));
        const float4* A = (const float4*)(emb + (size_t)i  * DDIM);
        const float4* P = (const float4*)(emb + (size_t)pi * DDIM);
        const float4* N = (const float4*)(emb + (size_t)ni * DDIM);

        float sap = 0.0f, san = 0.0f;
        #pragma unroll
        for (int q = 0; q < 4; q++) {
            float4 av = A[lane + 32 * q];
            float4 pv = P[lane + 32 * q];
            float4 nv = N[lane + 32 * q];
            float dd;
            dd = av.x - pv.x + 1e-6f; sap += dd * dd;
            dd = av.y - pv.y + 1e-6f; sap += dd * dd;
            dd = av.z - pv.z + 1e-6f; sap += dd * dd;
            dd = av.w - pv.w + 1e-6f; sap += dd * dd;
            dd = av.x - nv.x + 1e-6f; san += dd * dd;
            dd = av.y - nv.y + 1e-6f; san += dd * dd;
            dd = av.z - nv.z + 1e-6f; san += dd * dd;
            dd = av.w - nv.w + 1e-6f; san += dd * dd;
        }
        #pragma unroll
        for (int o = 16; o; o >>= 1) {
            sap += __shfl_xor_sync(0xffffffffu, sap, o);
            san += __shfl_xor_sync(0xffffffffu, san, o);
        }
        if (lane == 0) {
            float loss = fmaxf(sqrtf(sap) - sqrtf(san) + 1.0f, 0.0f);  // margin=1
            u64 fx = (u64)__double2ll_rn((double)loss * 4294967296.0);
            atomicAdd(&ssum, fx);
            atomicAdd(&scnt, 1u);
        }
    }
    __syncthreads();

    if (tid == 0) {
        if (scnt) {
            atomicAdd(&g_sumFix, ssum);
            atomicAdd(&g_cnt, scnt);
        }
        __threadfence();
        unsigned int ticket = atomicAdd(&g_done, 1u);
        if (ticket == gridDim.x - 1) {
            double s = (double)g_sumFix / 4294967296.0;
            float  c = (float)g_cnt;
            out[0] = (float)(s / (double)fmaxf(c, 1.0f));
        }
    }
}

// ---------------- launch ----------------
extern "C" void kernel_launch(void* const* d_in, const int* in_sizes, int n_in,
                              void* d_out, int out_size) {
    const float* emb    = (const float*)d_in[0];
    const int*   labels = (const int*)d_in[1];
    float*       out    = (float*)d_out;

    cudaFuncSetAttribute(mine_kernel,
                         cudaFuncAttributeMaxDynamicSharedMemorySize, DYN_SMEM);

    normalize_kernel<<<NROWS / 8, 256>>>(emb);
    mine_kernel<<<dim3(33, NBANDS), 256, DYN_SMEM>>>(labels);
    triplet_kernel<<<NROWS / 8, 256>>>(emb, out);
}

// round 13
// speedup vs baseline: 1.3105x; 1.3105x over previous
#include <cuda_runtime.h>
#include <cuda_fp16.h>
#include <math_constants.h>
#include <cstdint>

#define NROWS 8192
#define DDIM  512
#define MTILE 128
#define NTILE 128
#define BKH 64                            // halves per k-stage
#define NSTAGES (DDIM / BKH)              // 8
#define NBANDS (NROWS / NTILE)            // 64
#define SMS 72                            // smem row stride in halves (64 + 8 pad)
#define TILE_BYTES (MTILE * SMS * 2)      // 18432
#define DYN_SMEM (6 * TILE_BYTES)         // 3 stages x (A+B) = 110592

typedef unsigned long long u64;
#define KPOS_INIT 0xFFFFFFFFFFFFFFFFull
#define KNEG_INIT 0ull

// ---------------- scratch ----------------
__device__ __half g_unith[NROWS * DDIM];  // fp16 unit vectors (8 MB, L2-resident)
__device__ u64    g_posKey[NROWS];        // min over (ord(dot)<<32 | j)
__device__ u64    g_negKey[NROWS];        // max over (ord(dot)<<32 | (~0u - j))
__device__ u64    g_sumFix;               // sum(loss * 2^32), order-independent
__device__ unsigned int g_cnt;
__device__ unsigned int g_done;

// ---------------- helpers ----------------
__device__ __forceinline__ uint32_t smem_u32(const void* p) {
    uint32_t a;
    asm("{ .reg .u64 t; cvta.to.shared.u64 t, %1; cvt.u32.u64 %0, t; }"
        : "=r"(a) : "l"(p));
    return a;
}

__device__ __forceinline__ void cp16(uint32_t dst, const void* src) {
    asm volatile("cp.async.cg.shared.global [%0], [%1], 16;"
                 :: "r"(dst), "l"(src));
}
#define CP_COMMIT() asm volatile("cp.async.commit_group;" ::: "memory")
#define CP_WAIT(n)  asm volatile("cp.async.wait_group %0;" :: "n"(n) : "memory")

__device__ __forceinline__ void ldm_x4(uint32_t* r, uint32_t addr) {
    asm volatile("ldmatrix.sync.aligned.m8n8.x4.shared.b16 {%0,%1,%2,%3}, [%4];"
                 : "=r"(r[0]), "=r"(r[1]), "=r"(r[2]), "=r"(r[3]) : "r"(addr));
}

// monotonic float -> uint mapping
__device__ __forceinline__ uint32_t ford(float f) {
    uint32_t u = __float_as_uint(f);
    return u ^ (uint32_t)(((int32_t)u >> 31) | 0x80000000);
}

__device__ __forceinline__ void mma_f16(float* c, const uint32_t* a,
                                        uint32_t b0, uint32_t b1) {
    asm volatile(
        "mma.sync.aligned.m16n8k16.row.col.f32.f16.f16.f32 "
        "{%0,%1,%2,%3}, {%4,%5,%6,%7}, {%8,%9}, {%0,%1,%2,%3};"
        : "+f"(c[0]), "+f"(c[1]), "+f"(c[2]), "+f"(c[3])
        : "r"(a[0]), "r"(a[1]), "r"(a[2]), "r"(a[3]), "r"(b0), "r"(b1));
}

// ---------------- kernel 1: normalize (warp per row, no barriers) ------------
__global__ void normalize_kernel(const float* __restrict__ emb) {
    int gw   = (blockIdx.x * blockDim.x + threadIdx.x) >> 5;   // row
    int lane = threadIdx.x & 31;
    if (gw >= NROWS) return;

    const float4* src = (const float4*)(emb + (size_t)gw * DDIM);
    float4 v[4];
    float s = 0.0f;
    #pragma unroll
    for (int i = 0; i < 4; i++) {
        v[i] = src[lane + 32 * i];
        s += v[i].x * v[i].x + v[i].y * v[i].y + v[i].z * v[i].z + v[i].w * v[i].w;
    }
    #pragma unroll
    for (int o = 16; o; o >>= 1) s += __shfl_xor_sync(0xffffffffu, s, o);
    float inv = 1.0f / fmaxf(sqrtf(s), 1e-8f);

    __half2* dst = (__half2*)(g_unith + (size_t)gw * DDIM);
    #pragma unroll
    for (int i = 0; i < 4; i++) {
        dst[(lane + 32 * i) * 2]     = __floats2half2_rn(v[i].x * inv, v[i].y * inv);
        dst[(lane + 32 * i) * 2 + 1] = __floats2half2_rn(v[i].z * inv, v[i].w * inv);
    }
    if (lane == 0) {
        g_posKey[gw] = KPOS_INIT;
        g_negKey[gw] = KNEG_INIT;
    }
    if (gw == 0 && lane == 0) { g_sumFix = 0ull; g_cnt = 0u; g_done = 0u; }
}

// ---------------- kernel 2: fp16 mma Gram, one 128x128 tile per CTA ----------
// grid (33, 64): bi = blockIdx.y, bj = (bi + d) % 64, d = blockIdx.x.
// Upper-triangle coverage; d==32 duplicates for bi>=32 are skipped.
// 3-stage cp.async pipeline (K=64/stage), single-entry B-fragment lookahead.
__global__ void __launch_bounds__(256)
mine_kernel(const int* __restrict__ labels) {
    extern __shared__ __half dyn[];
    __shared__ u64 rowPos[128], rowNeg[128], colPos[128], colNeg[128];
    __shared__ int lblI[128], lblJ[128];

    const int d  = blockIdx.x;
    const int bi = blockIdx.y;
    if (d == 32 && bi >= 32) return;
    const int bj = (bi + d) & (NBANDS - 1);
    const int i0 = bi * MTILE;
    const int j0 = bj * NTILE;

    const int tid  = threadIdx.x;
    const int lane = tid & 31;
    const int wid  = tid >> 5;
    const int gid  = lane >> 2;     // 0..7
    const int tig  = lane & 3;      // 0..3
    const int wr   = wid >> 1;      // 0..3 (row band: wr*32)
    const int wc   = wid & 1;       // 0..1 (col band: wc*64)

    if (tid < 128) {
        lblI[tid] = labels[i0 + tid];
        lblJ[tid] = labels[j0 + tid];
        rowPos[tid] = KPOS_INIT; rowNeg[tid] = KNEG_INIT;
        colPos[tid] = KPOS_INIT; colNeg[tid] = KNEG_INIT;
    }
    __syncthreads();

    int myLbl[2][2];
    #pragma unroll
    for (int mi = 0; mi < 2; mi++)
        #pragma unroll
        for (int h = 0; h < 2; h++)
            myLbl[mi][h] = lblI[wr * 32 + mi * 16 + h * 8 + gid];

    const uint32_t sbase = smem_u32(dyn);
    uint32_t abuf[3], bbuf[3];
    #pragma unroll
    for (int s = 0; s < 3; s++) {
        abuf[s] = sbase + s * TILE_BYTES;
        bbuf[s] = sbase + (3 + s) * TILE_BYTES;
    }

    // per-thread cp.async offsets: 256 threads = 32 rows x 8 cols of 16B
    const int ldrow = tid >> 3;               // 0..31 (x4 iters -> 128 rows)
    const int ldc   = tid & 7;                // 0..7
    uint32_t soff[4];
    #pragma unroll
    for (int it = 0; it < 4; it++)
        soff[it] = (uint32_t)((ldrow + it * 32) * SMS + ldc * 8) * 2u;

    // ldmatrix lane address bases (in halves)
    const int lr = lane & 7;
    const int rowA = wr * 32 + ((lane >> 3) & 1) * 8 + lr;  // + mi*16
    const int kA   = (lane >> 4) * 8;                        // + kk*16
    const int nB   = wc * 64 + (lane >> 4) * 8 + lr;         // + ni2*16
    const int kB   = ((lane >> 3) & 1) * 8;                  // + kk*16

    float acc[2][8][4];
    #pragma unroll
    for (int mi = 0; mi < 2; mi++)
        #pragma unroll
        for (int ni = 0; ni < 8; ni++)
            #pragma unroll
            for (int q = 0; q < 4; q++) acc[mi][ni][q] = 0.0f;

    // ---- prologue: commit stages 0 and 1 ----
    #pragma unroll
    for (int s = 0; s < 2; s++) {
        const int k0 = s * BKH;
        #pragma unroll
        for (int it = 0; it < 4; it++) {
            cp16(abuf[s] + soff[it], g_unith + (size_t)(i0 + ldrow + it * 32) * DDIM + k0 + ldc * 8);
            cp16(bbuf[s] + soff[it], g_unith + (size_t)(j0 + ldrow + it * 32) * DDIM + k0 + ldc * 8);
        }
        CP_COMMIT();
    }

    int buf = 0;
    for (int s = 0; s < NSTAGES; s++) {
        CP_WAIT(1);
        __syncthreads();   // publish stage s; all warps done reading buf of s-1

        if (s + 2 < NSTAGES) {
            const int nb = (buf + 2 >= 3) ? buf - 1 : buf + 2;
            const int k0 = (s + 2) * BKH;
            #pragma unroll
            for (int it = 0; it < 4; it++) {
                cp16(abuf[nb] + soff[it], g_unith + (size_t)(i0 + ldrow + it * 32) * DDIM + k0 + ldc * 8);
                cp16(bbuf[nb] + soff[it], g_unith + (size_t)(j0 + ldrow + it * 32) * DDIM + k0 + ldc * 8);
            }
            CP_COMMIT();
        } else {
            CP_COMMIT();   // keep group count in lockstep for CP_WAIT(1)
        }

        const uint32_t abase = abuf[buf];
        const uint32_t bbase = bbuf[buf];
        #pragma unroll
        for (int kk = 0; kk < 4; kk++) {
            const int ko = kk * 16;
            uint32_t a0[4], a1[4];
            ldm_x4(a0, abase + (uint32_t)((rowA)      * SMS + kA + ko) * 2u);
            ldm_x4(a1, abase + (uint32_t)((rowA + 16) * SMS + kA + ko) * 2u);
            // single-entry B lookahead: load b[ni2+1] before issuing ni2's MMAs
            uint32_t bcur[4], bnxt[4];
            ldm_x4(bcur, bbase + (uint32_t)((nB) * SMS + kB + ko) * 2u);
            #pragma unroll
            for (int ni2 = 0; ni2 < 4; ni2++) {
                if (ni2 < 3)
                    ldm_x4(bnxt, bbase + (uint32_t)((nB + (ni2 + 1) * 16) * SMS + kB + ko) * 2u);
                mma_f16(acc[0][2 * ni2],     a0, bcur[0], bcur[1]);
                mma_f16(acc[0][2 * ni2 + 1], a0, bcur[2], bcur[3]);
                mma_f16(acc[1][2 * ni2],     a1, bcur[0], bcur[1]);
                mma_f16(acc[1][2 * ni2 + 1], a1, bcur[2], bcur[3]);
                #pragma unroll
                for (int q = 0; q < 4; q++) bcur[q] = bnxt[q];
            }
        }
        buf = (buf + 1 >= 3) ? 0 : buf + 1;
    }

    // ---- row-side selection (rows of band bi) ----
    #pragma unroll
    for (int mi = 0; mi < 2; mi++) {
        #pragma unroll
        for (int h = 0; h < 2; h++) {
            int r   = wr * 32 + mi * 16 + h * 8 + gid;
            int gi  = i0 + r;
            int lbl = myLbl[mi][h];
            u64 pk = KPOS_INIT, nk = KNEG_INIT;
            #pragma unroll
            for (int ni = 0; ni < 8; ni++) {
                #pragma unroll
                for (int u = 0; u < 2; u++) {
                    int jc = wc * 64 + ni * 8 + tig * 2 + u;
                    int j  = j0 + jc;
                    u64 od = (u64)ford(acc[mi][ni][h * 2 + u]) << 32;
                    if (lblJ[jc] == lbl) {
                        if (j != gi) {
                            u64 k = od | (uint32_t)j;
                            if (k < pk) pk = k;
                        }
                    } else {
                        u64 k = od | (uint32_t)(0xFFFFFFFFu - j);
                        if (k > nk) nk = k;
                    }
                }
            }
            #pragma unroll
            for (int off = 2; off; off >>= 1) {
                u64 opk = __shfl_down_sync(0xffffffffu, pk, off, 4);
                u64 onk = __shfl_down_sync(0xffffffffu, nk, off, 4);
                if (opk < pk) pk = opk;
                if (onk > nk) nk = onk;
            }
            if (tig == 0) {
                if (pk != KPOS_INIT) atomicMin(&rowPos[r], pk);
                if (nk != KNEG_INIT) atomicMax(&rowNeg[r], nk);
            }
        }
    }

    // ---- column-side selection (rows of band bj, via transpose) ----
    #pragma unroll
    for (int ni = 0; ni < 8; ni++) {
        #pragma unroll
        for (int u = 0; u < 2; u++) {
            int jc = wc * 64 + ni * 8 + tig * 2 + u;
            int gj = j0 + jc;
            int lj = lblJ[jc];
            u64 pk = KPOS_INIT, nk = KNEG_INIT;
            #pragma unroll
            for (int mi = 0; mi < 2; mi++) {
                #pragma unroll
                for (int h = 0; h < 2; h++) {
                    int gi = i0 + wr * 32 + mi * 16 + h * 8 + gid;
                    u64 od = (u64)ford(acc[mi][ni][h * 2 + u]) << 32;
                    if (myLbl[mi][h] == lj) {
                        if (gi != gj) {
                            u64 k = od | (uint32_t)gi;
                            if (k < pk) pk = k;
                        }
                    } else {
                        u64 k = od | (uint32_t)(0xFFFFFFFFu - gi);
                        if (k > nk) nk = k;
                    }
                }
            }
            #pragma unroll
            for (int off = 16; off >= 4; off >>= 1) {
                u64 opk = __shfl_down_sync(0xffffffffu, pk, off);
                u64 onk = __shfl_down_sync(0xffffffffu, nk, off);
                if (opk < pk) pk = opk;
                if (onk > nk) nk = onk;
            }
            if (gid == 0) {
                if (pk != KPOS_INIT) atomicMin(&colPos[jc], pk);
                if (nk != KNEG_INIT) atomicMax(&colNeg[jc], nk);
            }
        }
    }
    __syncthreads();

    // ---- flush both bands (min/max idempotent -> diagonal overlap is safe) ----
    if (tid < 128) {
        u64 rp = rowPos[tid], rn = rowNeg[tid];
        u64 cp = colPos[tid], cn = colNeg[tid];
        if (rp != KPOS_INIT) atomicMin(&g_posKey[i0 + tid], rp);
        if (rn != KNEG_INIT) atomicMax(&g_negKey[i0 + tid], rn);
        if (cp != KPOS_INIT) atomicMin(&g_posKey[j0 + tid], cp);
        if (cn != KNEG_INIT) atomicMax(&g_negKey[j0 + tid], cn);
    }
}

// ---------------- kernel 3: triplet loss (warp per row) + fused reduction ----
__global__ void triplet_kernel(const float* __restrict__ emb, float* __restrict__ out) {
    __shared__ u64 ssum;
    __shared__ unsigned int scnt;
    int tid  = threadIdx.x;
    int lane = tid & 31;
    int i    = blockIdx.x * 8 + (tid >> 5);     // row handled by this warp

    if (tid == 0) { ssum = 0ull; scnt = 0u; }
    __syncthreads();

    u64 pk = g_posKey[i];
    u64 nk = g_negKey[i];
    bool valid = (pk != KPOS_INIT) && (nk != KNEG_INIT);
    if (valid) {
        int pi = (int)(uint32_t)(pk & 0xFFFFFFFFull);
        int ni = (int)(0xFFFFFFFFu - (uint32_t)(nk & 0xFFFFFFFFull));
        const float4* A = (const float4*)(emb + (size_t)i  * DDIM);
        const float4* P = (const float4*)(emb + (size_t)pi * DDIM);
        const float4* N = (const float4*)(emb + (size_t)ni * DDIM);

        float sap = 0.0f, san = 0.0f;
        #pragma unroll
        for (int q = 0; q < 4; q++) {
            float4 av = A[lane + 32 * q];
            float4 pv = P[lane + 32 * q];
            float4 nv = N[lane + 32 * q];
            float dd;
            dd = av.x - pv.x + 1e-6f; sap += dd * dd;
            dd = av.y - pv.y + 1e-6f; sap += dd * dd;
            dd = av.z - pv.z + 1e-6f; sap += dd * dd;
            dd = av.w - pv.w + 1e-6f; sap += dd * dd;
            dd = av.x - nv.x + 1e-6f; san += dd * dd;
            dd = av.y - nv.y + 1e-6f; san += dd * dd;
            dd = av.z - nv.z + 1e-6f; san += dd * dd;
            dd = av.w - nv.w + 1e-6f; san += dd * dd;
        }
        #pragma unroll
        for (int o = 16; o; o >>= 1) {
            sap += __shfl_xor_sync(0xffffffffu, sap, o);
            san += __shfl_xor_sync(0xffffffffu, san, o);
        }
        if (lane == 0) {
            float loss = fmaxf(sqrtf(sap) - sqrtf(san) + 1.0f, 0.0f);  // margin=1
            u64 fx = (u64)__double2ll_rn((double)loss * 4294967296.0);
            atomicAdd(&ssum, fx);
            atomicAdd(&scnt, 1u);
        }
    }
    __syncthreads();

    if (tid == 0) {
        if (scnt) {
            atomicAdd(&g_sumFix, ssum);
            atomicAdd(&g_cnt, scnt);
        }
        __threadfence();
        unsigned int ticket = atomicAdd(&g_done, 1u);
        if (ticket == gridDim.x - 1) {
            double s = (double)g_sumFix / 4294967296.0;
            float  c = (float)g_cnt;
            out[0] = (float)(s / (double)fmaxf(c, 1.0f));
        }
    }
}

// ---------------- launch ----------------
extern "C" void kernel_launch(void* const* d_in, const int* in_sizes, int n_in,
                              void* d_out, int out_size) {
    const float* emb    = (const float*)d_in[0];
    const int*   labels = (const int*)d_in[1];
    float*       out    = (float*)d_out;

    cudaFuncSetAttribute(mine_kernel,
                         cudaFuncAttributeMaxDynamicSharedMemorySize, DYN_SMEM);

    normalize_kernel<<<NROWS / 8, 256>>>(emb);
    mine_kernel<<<dim3(33, NBANDS), 256, DYN_SMEM>>>(labels);
    triplet_kernel<<<NROWS / 8, 256>>>(emb, out);
}

// round 14
// speedup vs baseline: 1.3647x; 1.0413x over previous
#include <cuda_runtime.h>
#include <cuda_fp16.h>
#include <math_constants.h>
#include <cstdint>

#define NROWS 8192
#define DDIM  512
#define MTILE 128
#define NTILE 128
#define BKH 32                            // halves per k-stage
#define NSTAGES (DDIM / BKH)              // 16
#define NBANDS (NROWS / NTILE)            // 64
#define SMS 40                            // smem row stride in halves (32 + 8 pad)
#define TILE_BYTES (MTILE * SMS * 2)      // 10240
#define DYN_SMEM (6 * TILE_BYTES)         // 3 stages x (A+B) = 61440

typedef unsigned long long u64;
#define KPOS_INIT 0xFFFFFFFFFFFFFFFFull
#define KNEG_INIT 0ull

// ---------------- scratch ----------------
__device__ __half g_unith[NROWS * DDIM];  // fp16 unit vectors (8 MB, L2-resident)
__device__ u64    g_posKey[NROWS];        // min over (ord(dot)<<32 | j)
__device__ u64    g_negKey[NROWS];        // max over (ord(dot)<<32 | (~0u - j))
__device__ u64    g_sumFix;               // sum(loss * 2^32), order-independent
__device__ unsigned int g_cnt;
__device__ unsigned int g_done;

// ---------------- helpers ----------------
__device__ __forceinline__ uint32_t smem_u32(const void* p) {
    uint32_t a;
    asm("{ .reg .u64 t; cvta.to.shared.u64 t, %1; cvt.u32.u64 %0, t; }"
        : "=r"(a) : "l"(p));
    return a;
}

__device__ __forceinline__ void cp16(uint32_t dst, const void* src) {
    asm volatile("cp.async.cg.shared.global [%0], [%1], 16;"
                 :: "r"(dst), "l"(src));
}
#define CP_COMMIT() asm volatile("cp.async.commit_group;" ::: "memory")
#define CP_WAIT(n)  asm volatile("cp.async.wait_group %0;" :: "n"(n) : "memory")

__device__ __forceinline__ void ldm_x4(uint32_t* r, uint32_t addr) {
    asm volatile("ldmatrix.sync.aligned.m8n8.x4.shared.b16 {%0,%1,%2,%3}, [%4];"
                 : "=r"(r[0]), "=r"(r[1]), "=r"(r[2]), "=r"(r[3]) : "r"(addr));
}

// monotonic float -> uint mapping
__device__ __forceinline__ uint32_t ford(float f) {
    uint32_t u = __float_as_uint(f);
    return u ^ (uint32_t)(((int32_t)u >> 31) | 0x80000000);
}

__device__ __forceinline__ void mma_f16(float* c, const uint32_t* a,
                                        uint32_t b0, uint32_t b1) {
    asm volatile(
        "mma.sync.aligned.m16n8k16.row.col.f32.f16.f16.f32 "
        "{%0,%1,%2,%3}, {%4,%5,%6,%7}, {%8,%9}, {%0,%1,%2,%3};"
        : "+f"(c[0]), "+f"(c[1]), "+f"(c[2]), "+f"(c[3])
        : "r"(a[0]), "r"(a[1]), "r"(a[2]), "r"(a[3]), "r"(b0), "r"(b1));
}

// ---------------- kernel 1: normalize (warp per row, no barriers) ------------
__global__ void normalize_kernel(const float* __restrict__ emb) {
    int gw   = (blockIdx.x * blockDim.x + threadIdx.x) >> 5;   // row
    int lane = threadIdx.x & 31;
    if (gw >= NROWS) return;

    const float4* src = (const float4*)(emb + (size_t)gw * DDIM);
    float4 v[4];
    float s = 0.0f;
    #pragma unroll
    for (int i = 0; i < 4; i++) {
        v[i] = src[lane + 32 * i];
        s += v[i].x * v[i].x + v[i].y * v[i].y + v[i].z * v[i].z + v[i].w * v[i].w;
    }
    #pragma unroll
    for (int o = 16; o; o >>= 1) s += __shfl_xor_sync(0xffffffffu, s, o);
    float inv = 1.0f / fmaxf(sqrtf(s), 1e-8f);

    __half2* dst = (__half2*)(g_unith + (size_t)gw * DDIM);
    #pragma unroll
    for (int i = 0; i < 4; i++) {
        dst[(lane + 32 * i) * 2]     = __floats2half2_rn(v[i].x * inv, v[i].y * inv);
        dst[(lane + 32 * i) * 2 + 1] = __floats2half2_rn(v[i].z * inv, v[i].w * inv);
    }
    if (lane == 0) {
        g_posKey[gw] = KPOS_INIT;
        g_negKey[gw] = KNEG_INIT;
    }
    if (gw == 0 && lane == 0) { g_sumFix = 0ull; g_cnt = 0u; g_done = 0u; }
}

// ---------------- kernel 2: fp16 mma Gram, one 128x128 tile per CTA ----------
// grid (33, 64): bi = blockIdx.y, bj = (bi + d) % 64, d = blockIdx.x.
// Upper-triangle coverage; d==32 duplicates for bi>=32 are skipped.
// 3-stage cp.async pipeline (K=32/stage), plain ldmatrix loop (best measured).
__global__ void __launch_bounds__(256)
mine_kernel(const int* __restrict__ labels) {
    extern __shared__ __half dyn[];
    __shared__ u64 rowPos[128], rowNeg[128], colPos[128], colNeg[128];
    __shared__ int lblI[128], lblJ[128];

    const int d  = blockIdx.x;
    const int bi = blockIdx.y;
    if (d == 32 && bi >= 32) return;
    const int bj = (bi + d) & (NBANDS - 1);
    const int i0 = bi * MTILE;
    const int j0 = bj * NTILE;

    const int tid  = threadIdx.x;
    const int lane = tid & 31;
    const int wid  = tid >> 5;
    const int gid  = lane >> 2;     // 0..7
    const int tig  = lane & 3;      // 0..3
    const int wr   = wid >> 1;      // 0..3 (row band: wr*32)
    const int wc   = wid & 1;       // 0..1 (col band: wc*64)

    if (tid < 128) {
        lblI[tid] = labels[i0 + tid];
        lblJ[tid] = labels[j0 + tid];
        rowPos[tid] = KPOS_INIT; rowNeg[tid] = KNEG_INIT;
        colPos[tid] = KPOS_INIT; colNeg[tid] = KNEG_INIT;
    }
    __syncthreads();

    int myLbl[2][2];
    #pragma unroll
    for (int mi = 0; mi < 2; mi++)
        #pragma unroll
        for (int h = 0; h < 2; h++)
            myLbl[mi][h] = lblI[wr * 32 + mi * 16 + h * 8 + gid];

    const uint32_t sbase = smem_u32(dyn);
    uint32_t abuf[3], bbuf[3];
    #pragma unroll
    for (int s = 0; s < 3; s++) {
        abuf[s] = sbase + s * TILE_BYTES;
        bbuf[s] = sbase + (3 + s) * TILE_BYTES;
    }

    // per-thread cp.async offsets: 256 threads = 64 rows x 4 cols of 16B
    const int ldrow = tid >> 2;               // 0..63 (x2 iters -> 128 rows)
    const int ldc   = tid & 3;                // 0..3
    const uint32_t soff0 = (uint32_t)(ldrow * SMS + ldc * 8) * 2u;
    const uint32_t soff1 = (uint32_t)((ldrow + 64) * SMS + ldc * 8) * 2u;

    // ldmatrix lane address bases (in halves)
    const int lr = lane & 7;
    const int rowA = wr * 32 + ((lane >> 3) & 1) * 8 + lr;  // + mi*16
    const int kA   = (lane >> 4) * 8;                        // + kk*16
    const int nB   = wc * 64 + (lane >> 4) * 8 + lr;         // + ni2*16
    const int kB   = ((lane >> 3) & 1) * 8;                  // + kk*16

    float acc[2][8][4];
    #pragma unroll
    for (int mi = 0; mi < 2; mi++)
        #pragma unroll
        for (int ni = 0; ni < 8; ni++)
            #pragma unroll
            for (int q = 0; q < 4; q++) acc[mi][ni][q] = 0.0f;

    // ---- prologue: commit stages 0 and 1 ----
    #pragma unroll
    for (int s = 0; s < 2; s++) {
        const int k0 = s * BKH;
        cp16(abuf[s] + soff0, g_unith + (size_t)(i0 + ldrow) * DDIM + k0 + ldc * 8);
        cp16(bbuf[s] + soff0, g_unith + (size_t)(j0 + ldrow) * DDIM + k0 + ldc * 8);
        cp16(abuf[s] + soff1, g_unith + (size_t)(i0 + 64 + ldrow) * DDIM + k0 + ldc * 8);
        cp16(bbuf[s] + soff1, g_unith + (size_t)(j0 + 64 + ldrow) * DDIM + k0 + ldc * 8);
        CP_COMMIT();
    }

    int buf = 0;
    for (int s = 0; s < NSTAGES; s++) {
        CP_WAIT(1);
        __syncthreads();   // publish stage s; all warps done reading buf of s-1

        if (s + 2 < NSTAGES) {
            const int nb = (buf + 2 >= 3) ? buf - 1 : buf + 2;
            const int k0 = (s + 2) * BKH;
            cp16(abuf[nb] + soff0, g_unith + (size_t)(i0 + ldrow) * DDIM + k0 + ldc * 8);
            cp16(bbuf[nb] + soff0, g_unith + (size_t)(j0 + ldrow) * DDIM + k0 + ldc * 8);
            cp16(abuf[nb] + soff1, g_unith + (size_t)(i0 + 64 + ldrow) * DDIM + k0 + ldc * 8);
            cp16(bbuf[nb] + soff1, g_unith + (size_t)(j0 + 64 + ldrow) * DDIM + k0 + ldc * 8);
            CP_COMMIT();
        } else {
            CP_COMMIT();   // keep group count in lockstep for CP_WAIT(1)
        }

        const uint32_t abase = abuf[buf];
        const uint32_t bbase = bbuf[buf];
        #pragma unroll
        for (int kk = 0; kk < 2; kk++) {
            uint32_t a0[4], a1[4];
            ldm_x4(a0, abase + (uint32_t)((rowA)      * SMS + kA + kk * 16) * 2u);
            ldm_x4(a1, abase + (uint32_t)((rowA + 16) * SMS + kA + kk * 16) * 2u);
            #pragma unroll
            for (int ni2 = 0; ni2 < 4; ni2++) {
                uint32_t b[4];
                ldm_x4(b, bbase + (uint32_t)((nB + ni2 * 16) * SMS + kB + kk * 16) * 2u);
                mma_f16(acc[0][2 * ni2],     a0, b[0], b[1]);
                mma_f16(acc[0][2 * ni2 + 1], a0, b[2], b[3]);
                mma_f16(acc[1][2 * ni2],     a1, b[0], b[1]);
                mma_f16(acc[1][2 * ni2 + 1], a1, b[2], b[3]);
            }
        }
        buf = (buf + 1 >= 3) ? 0 : buf + 1;
    }

    // ---- row-side selection (rows of band bi) ----
    #pragma unroll
    for (int mi = 0; mi < 2; mi++) {
        #pragma unroll
        for (int h = 0; h < 2; h++) {
            int r   = wr * 32 + mi * 16 + h * 8 + gid;
            int gi  = i0 + r;
            int lbl = myLbl[mi][h];
            u64 pk = KPOS_INIT, nk = KNEG_INIT;
            #pragma unroll
            for (int ni = 0; ni < 8; ni++) {
                #pragma unroll
                for (int u = 0; u < 2; u++) {
                    int jc = wc * 64 + ni * 8 + tig * 2 + u;
                    int j  = j0 + jc;
                    u64 od = (u64)ford(acc[mi][ni][h * 2 + u]) << 32;
                    if (lblJ[jc] == lbl) {
                        if (j != gi) {
                            u64 k = od | (uint32_t)j;
                            if (k < pk) pk = k;
                        }
                    } else {
                        u64 k = od | (uint32_t)(0xFFFFFFFFu - j);
                        if (k > nk) nk = k;
                    }
                }
            }
            #pragma unroll
            for (int off = 2; off; off >>= 1) {
                u64 opk = __shfl_down_sync(0xffffffffu, pk, off, 4);
                u64 onk = __shfl_down_sync(0xffffffffu, nk, off, 4);
                if (opk < pk) pk = opk;
                if (onk > nk) nk = onk;
            }
            if (tig == 0) {
                if (pk != KPOS_INIT) atomicMin(&rowPos[r], pk);
                if (nk != KNEG_INIT) atomicMax(&rowNeg[r], nk);
            }
        }
    }

    // ---- column-side selection (rows of band bj, via transpose) ----
    #pragma unroll
    for (int ni = 0; ni < 8; ni++) {
        #pragma unroll
        for (int u = 0; u < 2; u++) {
            int jc = wc * 64 + ni * 8 + tig * 2 + u;
            int gj = j0 + jc;
            int lj = lblJ[jc];
            u64 pk = KPOS_INIT, nk = KNEG_INIT;
            #pragma unroll
            for (int mi = 0; mi < 2; mi++) {
                #pragma unroll
                for (int h = 0; h < 2; h++) {
                    int gi = i0 + wr * 32 + mi * 16 + h * 8 + gid;
                    u64 od = (u64)ford(acc[mi][ni][h * 2 + u]) << 32;
                    if (myLbl[mi][h] == lj) {
                        if (gi != gj) {
                            u64 k = od | (uint32_t)gi;
                            if (k < pk) pk = k;
                        }
                    } else {
                        u64 k = od | (uint32_t)(0xFFFFFFFFu - gi);
                        if (k > nk) nk = k;
                    }
                }
            }
            #pragma unroll
            for (int off = 16; off >= 4; off >>= 1) {
                u64 opk = __shfl_down_sync(0xffffffffu, pk, off);
                u64 onk = __shfl_down_sync(0xffffffffu, nk, off);
                if (opk < pk) pk = opk;
                if (onk > nk) nk = onk;
            }
            if (gid == 0) {
                if (pk != KPOS_INIT) atomicMin(&colPos[jc], pk);
                if (nk != KNEG_INIT) atomicMax(&colNeg[jc], nk);
            }
        }
    }
    __syncthreads();

    // ---- flush both bands (min/max idempotent -> diagonal overlap is safe) ----
    if (tid < 128) {
        u64 rp = rowPos[tid], rn = rowNeg[tid];
        u64 cp = colPos[tid], cn = colNeg[tid];
        if (rp != KPOS_INIT) atomicMin(&g_posKey[i0 + tid], rp);
        if (rn != KNEG_INIT) atomicMax(&g_negKey[i0 + tid], rn);
        if (cp != KPOS_INIT) atomicMin(&g_posKey[j0 + tid], cp);
        if (cn != KNEG_INIT) atomicMax(&g_negKey[j0 + tid], cn);
    }
}

// ---------------- kernel 3: triplet loss (warp per row) + fused reduction ----
__global__ void triplet_kernel(const float* __restrict__ emb, float* __restrict__ out) {
    __shared__ u64 ssum;
    __shared__ unsigned int scnt;
    int tid  = threadIdx.x;
    int lane = tid & 31;
    int i    = blockIdx.x * 8 + (tid >> 5);     // row handled by this warp

    if (tid == 0) { ssum = 0ull; scnt = 0u; }
    __syncthreads();

    u64 pk = g_posKey[i];
    u64 nk = g_negKey[i];
    bool valid = (pk != KPOS_INIT) && (nk != KNEG_INIT);
    if (valid) {
        int pi = (int)(uint32_t)(pk & 0xFFFFFFFFull);
        int ni = (int)(0xFFFFFFFFu - (uint32_t)(nk & 0xFFFFFFFFull));
        const float4* A = (const float4*)(emb + (size_t)i  * DDIM);
        const float4* P = (const float4*)(emb + (size_t)pi * DDIM);
        const float4* N = (const float4*)(emb + (size_t)ni * DDIM);

        float sap = 0.0f, san = 0.0f;
        #pragma unroll
        for (int q = 0; q < 4; q++) {
            float4 av = A[lane + 32 * q];
            float4 pv = P[lane + 32 * q];
            float4 nv = N[lane + 32 * q];
            float dd;
            dd = av.x - pv.x + 1e-6f; sap += dd * dd;
            dd = av.y - pv.y + 1e-6f; sap += dd * dd;
            dd = av.z - pv.z + 1e-6f; sap += dd * dd;
            dd = av.w - pv.w + 1e-6f; sap += dd * dd;
            dd = av.x - nv.x + 1e-6f; san += dd * dd;
            dd = av.y - nv.y + 1e-6f; san += dd * dd;
            dd = av.z - nv.z + 1e-6f; san += dd * dd;
            dd = av.w - nv.w + 1e-6f; san += dd * dd;
        }
        #pragma unroll
        for (int o = 16; o; o >>= 1) {
            sap += __shfl_xor_sync(0xffffffffu, sap, o);
            san += __shfl_xor_sync(0xffffffffu, san, o);
        }
        if (lane == 0) {
            float loss = fmaxf(sqrtf(sap) - sqrtf(san) + 1.0f, 0.0f);  // margin=1
            u64 fx = (u64)__double2ll_rn((double)loss * 4294967296.0);
            atomicAdd(&ssum, fx);
            atomicAdd(&scnt, 1u);
        }
    }
    __syncthreads();

    if (tid == 0) {
        if (scnt) {
            atomicAdd(&g_sumFix, ssum);
            atomicAdd(&g_cnt, scnt);
        }
        __threadfence();
        unsigned int ticket = atomicAdd(&g_done, 1u);
        if (ticket == gridDim.x - 1) {
            double s = (double)g_sumFix / 4294967296.0;
            float  c = (float)g_cnt;
            out[0] = (float)(s / (double)fmaxf(c, 1.0f));
        }
    }
}

// ---------------- launch ----------------
extern "C" void kernel_launch(void* const* d_in, const int* in_sizes, int n_in,
                              void* d_out, int out_size) {
    const float* emb    = (const float*)d_in[0];
    const int*   labels = (const int*)d_in[1];
    float*       out    = (float*)d_out;

    cudaFuncSetAttribute(mine_kernel,
                         cudaFuncAttributeMaxDynamicSharedMemorySize, DYN_SMEM);

    normalize_kernel<<<NROWS / 8, 256>>>(emb);
    mine_kernel<<<dim3(33, NBANDS), 256, DYN_SMEM>>>(labels);
    triplet_kernel<<<NROWS / 8, 256>>>(emb, out);
}

// round 16
// speedup vs baseline: 1.3791x; 1.0106x over previous
#include <cuda_runtime.h>
#include <cuda_fp16.h>
#include <math_constants.h>
#include <cstdint>

#define NROWS 8192
#define DDIM  512
#define MTILE 128
#define NTILE 128
#define BKH 32                            // halves per k-stage
#define NSTAGES (DDIM / BKH)              // 16
#define NBANDS (NROWS / NTILE)            // 64
#define SMS 40                            // smem row stride in halves (32 + 8 pad)
#define TILE_BYTES (MTILE * SMS * 2)      // 10240
#define NBUF 4
#define DYN_SMEM (2 * NBUF * TILE_BYTES)  // 4 stages x (A+B) = 81920

typedef unsigned long long u64;
#define KPOS_INIT 0xFFFFFFFFFFFFFFFFull
#define KNEG_INIT 0ull

// ---------------- scratch ----------------
__device__ __half g_unith[NROWS * DDIM];  // fp16 unit vectors (8 MB, L2-resident)
__device__ u64    g_posKey[NROWS];        // min over (ord(dot)<<32 | j)
__device__ u64    g_negKey[NROWS];        // max over (ord(dot)<<32 | (~0u - j))
__device__ u64    g_sumFix;               // sum(loss * 2^32), order-independent
__device__ unsigned int g_cnt;
__device__ unsigned int g_done;

// ---------------- helpers ----------------
__device__ __forceinline__ uint32_t smem_u32(const void* p) {
    uint32_t a;
    asm("{ .reg .u64 t; cvta.to.shared.u64 t, %1; cvt.u32.u64 %0, t; }"
        : "=r"(a) : "l"(p));
    return a;
}

__device__ __forceinline__ void cp16(uint32_t dst, const void* src) {
    asm volatile("cp.async.cg.shared.global [%0], [%1], 16;"
                 :: "r"(dst), "l"(src));
}
#define CP_COMMIT() asm volatile("cp.async.commit_group;" ::: "memory")
#define CP_WAIT(n)  asm volatile("cp.async.wait_group %0;" :: "n"(n) : "memory")

__device__ __forceinline__ void ldm_x4(uint32_t* r, uint32_t addr) {
    asm volatile("ldmatrix.sync.aligned.m8n8.x4.shared.b16 {%0,%1,%2,%3}, [%4];"
                 : "=r"(r[0]), "=r"(r[1]), "=r"(r[2]), "=r"(r[3]) : "r"(addr));
}

// monotonic float -> uint mapping
__device__ __forceinline__ uint32_t ford(float f) {
    uint32_t u = __float_as_uint(f);
    return u ^ (uint32_t)(((int32_t)u >> 31) | 0x80000000);
}

__device__ __forceinline__ void mma_f16(float* c, const uint32_t* a,
                                        uint32_t b0, uint32_t b1) {
    asm volatile(
        "mma.sync.aligned.m16n8k16.row.col.f32.f16.f16.f32 "
        "{%0,%1,%2,%3}, {%4,%5,%6,%7}, {%8,%9}, {%0,%1,%2,%3};"
        : "+f"(c[0]), "+f"(c[1]), "+f"(c[2]), "+f"(c[3])
        : "r"(a[0]), "r"(a[1]), "r"(a[2]), "r"(a[3]), "r"(b0), "r"(b1));
}

// ---------------- kernel 1: normalize (warp per row, no barriers) ------------
__global__ void normalize_kernel(const float* __restrict__ emb) {
    int gw   = (blockIdx.x * blockDim.x + threadIdx.x) >> 5;   // row
    int lane = threadIdx.x & 31;
    if (gw >= NROWS) return;

    const float4* src = (const float4*)(emb + (size_t)gw * DDIM);
    float4 v[4];
    float s = 0.0f;
    #pragma unroll
    for (int i = 0; i < 4; i++) {
        v[i] = src[lane + 32 * i];
        s += v[i].x * v[i].x + v[i].y * v[i].y + v[i].z * v[i].z + v[i].w * v[i].w;
    }
    #pragma unroll
    for (int o = 16; o; o >>= 1) s += __shfl_xor_sync(0xffffffffu, s, o);
    float inv = 1.0f / fmaxf(sqrtf(s), 1e-8f);

    __half2* dst = (__half2*)(g_unith + (size_t)gw * DDIM);
    #pragma unroll
    for (int i = 0; i < 4; i++) {
        dst[(lane + 32 * i) * 2]     = __floats2half2_rn(v[i].x * inv, v[i].y * inv);
        dst[(lane + 32 * i) * 2 + 1] = __floats2half2_rn(v[i].z * inv, v[i].w * inv);
    }
    if (lane == 0) {
        g_posKey[gw] = KPOS_INIT;
        g_negKey[gw] = KNEG_INIT;
    }
    if (gw == 0 && lane == 0) { g_sumFix = 0ull; g_cnt = 0u; g_done = 0u; }
}

// ---------------- kernel 2: fp16 mma Gram, one 128x128 tile per CTA ----------
// grid (33, 64): bi = blockIdx.y, bj = (bi + d) % 64, d = blockIdx.x.
// Upper-triangle coverage; d==32 duplicates for bi>=32 are skipped.
// 4-buffer cp.async pipeline, prefetch ISSUED BEFORE the wait (buffer (s+2)%4
// was last read in stage s-2, already fenced by the s-1 barrier).
__global__ void __launch_bounds__(256)
mine_kernel(const int* __restrict__ labels) {
    extern __shared__ __half dyn[];
    __shared__ u64 rowPos[128], rowNeg[128], colPos[128], colNeg[128];
    __shared__ int lblI[128], lblJ[128];

    const int d  = blockIdx.x;
    const int bi = blockIdx.y;
    if (d == 32 && bi >= 32) return;
    const int bj = (bi + d) & (NBANDS - 1);
    const int i0 = bi * MTILE;
    const int j0 = bj * NTILE;

    const int tid  = threadIdx.x;
    const int lane = tid & 31;
    const int wid  = tid >> 5;
    const int gid  = lane >> 2;     // 0..7
    const int tig  = lane & 3;      // 0..3
    const int wr   = wid >> 1;      // 0..3 (row band: wr*32)
    const int wc   = wid & 1;       // 0..1 (col band: wc*64)

    if (tid < 128) {
        lblI[tid] = labels[i0 + tid];
        lblJ[tid] = labels[j0 + tid];
        rowPos[tid] = KPOS_INIT; rowNeg[tid] = KNEG_INIT;
        colPos[tid] = KPOS_INIT; colNeg[tid] = KNEG_INIT;
    }
    __syncthreads();

    int myLbl[2][2];
    #pragma unroll
    for (int mi = 0; mi < 2; mi++)
        #pragma unroll
        for (int h = 0; h < 2; h++)
            myLbl[mi][h] = lblI[wr * 32 + mi * 16 + h * 8 + gid];

    const uint32_t sbase = smem_u32(dyn);
    uint32_t abuf[NBUF], bbuf[NBUF];
    #pragma unroll
    for (int s = 0; s < NBUF; s++) {
        abuf[s] = sbase + s * TILE_BYTES;
        bbuf[s] = sbase + (NBUF + s) * TILE_BYTES;
    }

    // per-thread cp.async offsets: 256 threads = 64 rows x 4 cols of 16B
    const int ldrow = tid >> 2;               // 0..63 (x2 iters -> 128 rows)
    const int ldc   = tid & 3;                // 0..3
    const uint32_t soff0 = (uint32_t)(ldrow * SMS + ldc * 8) * 2u;
    const uint32_t soff1 = (uint32_t)((ldrow + 64) * SMS + ldc * 8) * 2u;

    // ldmatrix lane address bases (in halves)
    const int lr = lane & 7;
    const int rowA = wr * 32 + ((lane >> 3) & 1) * 8 + lr;  // + mi*16
    const int kA   = (lane >> 4) * 8;                        // + kk*16
    const int nB   = wc * 64 + (lane >> 4) * 8 + lr;         // + ni2*16
    const int kB   = ((lane >> 3) & 1) * 8;                  // + kk*16

    float acc[2][8][4];
    #pragma unroll
    for (int mi = 0; mi < 2; mi++)
        #pragma unroll
        for (int ni = 0; ni < 8; ni++)
            #pragma unroll
            for (int q = 0; q < 4; q++) acc[mi][ni][q] = 0.0f;

    // ---- prologue: commit stages 0 and 1 ----
    #pragma unroll
    for (int s = 0; s < 2; s++) {
        const int k0 = s * BKH;
        cp16(abuf[s] + soff0, g_unith + (size_t)(i0 + ldrow) * DDIM + k0 + ldc * 8);
        cp16(bbuf[s] + soff0, g_unith + (size_t)(j0 + ldrow) * DDIM + k0 + ldc * 8);
        cp16(abuf[s] + soff1, g_unith + (size_t)(i0 + 64 + ldrow) * DDIM + k0 + ldc * 8);
        cp16(bbuf[s] + soff1, g_unith + (size_t)(j0 + 64 + ldrow) * DDIM + k0 + ldc * 8);
        CP_COMMIT();
    }

    for (int s = 0; s < NSTAGES; s++) {
        // prefetch stage s+2 BEFORE the wait: its buffer was last read in
        // stage s-2, and the barrier at top of stage s-1 fenced those reads.
        if (s + 2 < NSTAGES) {
            const int nb = (s + 2) & (NBUF - 1);
            const int k0 = (s + 2) * BKH;
            cp16(abuf[nb] + soff0, g_unith + (size_t)(i0 + ldrow) * DDIM + k0 + ldc * 8);
            cp16(bbuf[nb] + soff0, g_unith + (size_t)(j0 + ldrow) * DDIM + k0 + ldc * 8);
            cp16(abuf[nb] + soff1, g_unith + (size_t)(i0 + 64 + ldrow) * DDIM + k0 + ldc * 8);
            cp16(bbuf[nb] + soff1, g_unith + (size_t)(j0 + 64 + ldrow) * DDIM + k0 + ldc * 8);
        }
        CP_COMMIT();       // one group per stage (empty in tail) keeps counts aligned

        CP_WAIT(2);        // 3 groups pending max -> group s complete
        __syncthreads();   // publish stage s; fence reads of stage s-1

        const uint32_t abase = abuf[s & (NBUF - 1)];
        const uint32_t bbase = bbuf[s & (NBUF - 1)];
        #pragma unroll
        for (int kk = 0; kk < 2; kk++) {
            uint32_t a0[4], a1[4];
            ldm_x4(a0, abase + (uint32_t)((rowA)      * SMS + kA + kk * 16) * 2u);
            ldm_x4(a1, abase + (uint32_t)((rowA + 16) * SMS + kA + kk * 16) * 2u);
            #pragma unroll
            for (int ni2 = 0; ni2 < 4; ni2++) {
                uint32_t b[4];
                ldm_x4(b, bbase + (uint32_t)((nB + ni2 * 16) * SMS + kB + kk * 16) * 2u);
                mma_f16(acc[0][2 * ni2],     a0, b[0], b[1]);
                mma_f16(acc[0][2 * ni2 + 1], a0, b[2], b[3]);
                mma_f16(acc[1][2 * ni2],     a1, b[0], b[1]);
                mma_f16(acc[1][2 * ni2 + 1], a1, b[2], b[3]);
            }
        }
    }

    // ---- row-side selection (rows of band bi) ----
    #pragma unroll
    for (int mi = 0; mi < 2; mi++) {
        #pragma unroll
        for (int h = 0; h < 2; h++) {
            int r   = wr * 32 + mi * 16 + h * 8 + gid;
            int gi  = i0 + r;
            int lbl = myLbl[mi][h];
            u64 pk = KPOS_INIT, nk = KNEG_INIT;
            #pragma unroll
            for (int ni = 0; ni < 8; ni++) {
                #pragma unroll
                for (int u = 0; u < 2; u++) {
                    int jc = wc * 64 + ni * 8 + tig * 2 + u;
                    int j  = j0 + jc;
                    u64 od = (u64)ford(acc[mi][ni][h * 2 + u]) << 32;
                    if (lblJ[jc] == lbl) {
                        if (j != gi) {
                            u64 k = od | (uint32_t)j;
                            if (k < pk) pk = k;
                        }
                    } else {
                        u64 k = od | (uint32_t)(0xFFFFFFFFu - j);
                        if (k > nk) nk = k;
                    }
                }
            }
            #pragma unroll
            for (int off = 2; off; off >>= 1) {
                u64 opk = __shfl_down_sync(0xffffffffu, pk, off, 4);
                u64 onk = __shfl_down_sync(0xffffffffu, nk, off, 4);
                if (opk < pk) pk = opk;
                if (onk > nk) nk = onk;
            }
            if (tig == 0) {
                if (pk != KPOS_INIT) atomicMin(&rowPos[r], pk);
                if (nk != KNEG_INIT) atomicMax(&rowNeg[r], nk);
            }
        }
    }

    // ---- column-side selection (rows of band bj, via transpose) ----
    #pragma unroll
    for (int ni = 0; ni < 8; ni++) {
        #pragma unroll
        for (int u = 0; u < 2; u++) {
            int jc = wc * 64 + ni * 8 + tig * 2 + u;
            int gj = j0 + jc;
            int lj = lblJ[jc];
            u64 pk = KPOS_INIT, nk = KNEG_INIT;
            #pragma unroll
            for (int mi = 0; mi < 2; mi++) {
                #pragma unroll
                for (int h = 0; h < 2; h++) {
                    int gi = i0 + wr * 32 + mi * 16 + h * 8 + gid;
                    u64 od = (u64)ford(acc[mi][ni][h * 2 + u]) << 32;
                    if (myLbl[mi][h] == lj) {
                        if (gi != gj) {
                            u64 k = od | (uint32_t)gi;
                            if (k < pk) pk = k;
                        }
                    } else {
                        u64 k = od | (uint32_t)(0xFFFFFFFFu - gi);
                        if (k > nk) nk = k;
                    }
                }
            }
            #pragma unroll
            for (int off = 16; off >= 4; off >>= 1) {
                u64 opk = __shfl_down_sync(0xffffffffu, pk, off);
                u64 onk = __shfl_down_sync(0xffffffffu, nk, off);
                if (opk < pk) pk = opk;
                if (onk > nk) nk = onk;
            }
            if (gid == 0) {
                if (pk != KPOS_INIT) atomicMin(&colPos[jc], pk);
                if (nk != KNEG_INIT) atomicMax(&colNeg[jc], nk);
            }
        }
    }
    __syncthreads();

    // ---- flush both bands (min/max idempotent -> diagonal overlap is safe) ----
    if (tid < 128) {
        u64 rp = rowPos[tid], rn = rowNeg[tid];
        u64 cp = colPos[tid], cn = colNeg[tid];
        if (rp != KPOS_INIT) atomicMin(&g_posKey[i0 + tid], rp);
        if (rn != KNEG_INIT) atomicMax(&g_negKey[i0 + tid], rn);
        if (cp != KPOS_INIT) atomicMin(&g_posKey[j0 + tid], cp);
        if (cn != KNEG_INIT) atomicMax(&g_negKey[j0 + tid], cn);
    }
}

// ---------------- kernel 3: triplet loss (warp per row) + fused reduction ----
__global__ void triplet_kernel(const float* __restrict__ emb, float* __restrict__ out) {
    __shared__ u64 ssum;
    __shared__ unsigned int scnt;
    int tid  = threadIdx.x;
    int lane = tid & 31;
    int i    = blockIdx.x * 8 + (tid >> 5);     // row handled by this warp

    if (tid == 0) { ssum = 0ull; scnt = 0u; }
    __syncthreads();

    u64 pk = g_posKey[i];
    u64 nk = g_negKey[i];
    bool valid = (pk != KPOS_INIT) && (nk != KNEG_INIT);
    if (valid) {
        int pi = (int)(uint32_t)(pk & 0xFFFFFFFFull);
        int ni = (int)(0xFFFFFFFFu - (uint32_t)(nk & 0xFFFFFFFFull));
        const float4* A = (const float4*)(emb + (size_t)i  * DDIM);
        const float4* P = (const float4*)(emb + (size_t)pi * DDIM);
        const float4* N = (const float4*)(emb + (size_t)ni * DDIM);

        float sap = 0.0f, san = 0.0f;
        #pragma unroll
        for (int q = 0; q < 4; q++) {
            float4 av = A[lane + 32 * q];
            float4 pv = P[lane + 32 * q];
            float4 nv = N[lane + 32 * q];
            float dd;
            dd = av.x - pv.x + 1e-6f; sap += dd * dd;
            dd = av.y - pv.y + 1e-6f; sap += dd * dd;
            dd = av.z - pv.z + 1e-6f; sap += dd * dd;
            dd = av.w - pv.w + 1e-6f; sap += dd * dd;
            dd = av.x - nv.x + 1e-6f; san += dd * dd;
            dd = av.y - nv.y + 1e-6f; san += dd * dd;
            dd = av.z - nv.z + 1e-6f; san += dd * dd;
            dd = av.w - nv.w + 1e-6f; san += dd * dd;
        }
        #pragma unroll
        for (int o = 16; o; o >>= 1) {
            sap += __shfl_xor_sync(0xffffffffu, sap, o);
            san += __shfl_xor_sync(0xffffffffu, san, o);
        }
        if (lane == 0) {
            float loss = fmaxf(sqrtf(sap) - sqrtf(san) + 1.0f, 0.0f);  // margin=1
            u64 fx = (u64)__double2ll_rn((double)loss * 4294967296.0);
            atomicAdd(&ssum, fx);
            atomicAdd(&scnt, 1u);
        }
    }
    __syncthreads();

    if (tid == 0) {
        if (scnt) {
            atomicAdd(&g_sumFix, ssum);
            atomicAdd(&g_cnt, scnt);
        }
        __threadfence();
        unsigned int ticket = atomicAdd(&g_done, 1u);
        if (ticket == gridDim.x - 1) {
            double s = (double)g_sumFix / 4294967296.0;
            float  c = (float)g_cnt;
            out[0] = (float)(s / (double)fmaxf(c, 1.0f));
        }
    }
}

// ---------------- launch ----------------
extern "C" void kernel_launch(void* const* d_in, const int* in_sizes, int n_in,
                              void* d_out, int out_size) {
    const float* emb    = (const float*)d_in[0];
    const int*   labels = (const int*)d_in[1];
    float*       out    = (float*)d_out;

    cudaFuncSetAttribute(mine_kernel,
                         cudaFuncAttributeMaxDynamicSharedMemorySize, DYN_SMEM);

    normalize_kernel<<<NROWS / 8, 256>>>(emb);
    mine_kernel<<<dim3(33, NBANDS), 256, DYN_SMEM>>>(labels);
    triplet_kernel<<<NROWS / 8, 256>>>(emb, out);
}

// round 17
// speedup vs baseline: 1.3976x; 1.0134x over previous
#include <cuda_runtime.h>
#include <cuda_fp16.h>
#include <math_constants.h>
#include <cstdint>

#define NROWS 8192
#define DDIM  512
#define MTILE 128
#define NTILE 128
#define BKH 32                            // halves per k-stage
#define NSTAGES (DDIM / BKH)              // 16
#define NBANDS (NROWS / NTILE)            // 64
#define SMS 40                            // smem row stride in halves (32 + 8 pad)
#define TILE_BYTES (MTILE * SMS * 2)      // 10240
#define NBUF 4
#define DYN_SMEM (2 * NBUF * TILE_BYTES)  // 4 stages x (A+B) = 81920

typedef unsigned long long u64;
#define KPOS_INIT 0xFFFFFFFFFFFFFFFFull
#define KNEG_INIT 0ull

// ---------------- scratch ----------------
__device__ __half g_unith[NROWS * DDIM];  // fp16 unit vectors (8 MB, L2-resident)
__device__ u64    g_posKey[NROWS];        // min over (ord(dot)<<32 | j)
__device__ u64    g_negKey[NROWS];        // max over (ord(dot)<<32 | (~0u - j))
__device__ u64    g_sumFix;               // sum(loss * 2^32), order-independent
__device__ unsigned int g_cnt;
__device__ unsigned int g_done;

// ---------------- helpers ----------------
__device__ __forceinline__ uint32_t smem_u32(const void* p) {
    uint32_t a;
    asm("{ .reg .u64 t; cvta.to.shared.u64 t, %1; cvt.u32.u64 %0, t; }"
        : "=r"(a) : "l"(p));
    return a;
}

__device__ __forceinline__ void cp16(uint32_t dst, const void* src) {
    asm volatile("cp.async.cg.shared.global [%0], [%1], 16;"
                 :: "r"(dst), "l"(src));
}
#define CP_COMMIT() asm volatile("cp.async.commit_group;" ::: "memory")
#define CP_WAIT(n)  asm volatile("cp.async.wait_group %0;" :: "n"(n) : "memory")

__device__ __forceinline__ void ldm_x4(uint32_t* r, uint32_t addr) {
    asm volatile("ldmatrix.sync.aligned.m8n8.x4.shared.b16 {%0,%1,%2,%3}, [%4];"
                 : "=r"(r[0]), "=r"(r[1]), "=r"(r[2]), "=r"(r[3]) : "r"(addr));
}

// monotonic float -> uint mapping
__device__ __forceinline__ uint32_t ford(float f) {
    uint32_t u = __float_as_uint(f);
    return u ^ (uint32_t)(((int32_t)u >> 31) | 0x80000000);
}

__device__ __forceinline__ void mma_f16(float* c, const uint32_t* a,
                                        uint32_t b0, uint32_t b1) {
    asm volatile(
        "mma.sync.aligned.m16n8k16.row.col.f32.f16.f16.f32 "
        "{%0,%1,%2,%3}, {%4,%5,%6,%7}, {%8,%9}, {%0,%1,%2,%3};"
        : "+f"(c[0]), "+f"(c[1]), "+f"(c[2]), "+f"(c[3])
        : "r"(a[0]), "r"(a[1]), "r"(a[2]), "r"(a[3]), "r"(b0), "r"(b1));
}

// ---------------- kernel 1: normalize (warp per row, no barriers) ------------
__global__ void normalize_kernel(const float* __restrict__ emb) {
    int gw   = (blockIdx.x * blockDim.x + threadIdx.x) >> 5;   // row
    int lane = threadIdx.x & 31;
    if (gw >= NROWS) return;

    const float4* src = (const float4*)(emb + (size_t)gw * DDIM);
    float4 v[4];
    float s = 0.0f;
    #pragma unroll
    for (int i = 0; i < 4; i++) {
        v[i] = src[lane + 32 * i];
        s += v[i].x * v[i].x + v[i].y * v[i].y + v[i].z * v[i].z + v[i].w * v[i].w;
    }
    #pragma unroll
    for (int o = 16; o; o >>= 1) s += __shfl_xor_sync(0xffffffffu, s, o);
    float inv = 1.0f / fmaxf(sqrtf(s), 1e-8f);

    __half2* dst = (__half2*)(g_unith + (size_t)gw * DDIM);
    #pragma unroll
    for (int i = 0; i < 4; i++) {
        dst[(lane + 32 * i) * 2]     = __floats2half2_rn(v[i].x * inv, v[i].y * inv);
        dst[(lane + 32 * i) * 2 + 1] = __floats2half2_rn(v[i].z * inv, v[i].w * inv);
    }
    if (lane == 0) {
        g_posKey[gw] = KPOS_INIT;
        g_negKey[gw] = KNEG_INIT;
    }
    if (gw == 0 && lane == 0) { g_sumFix = 0ull; g_cnt = 0u; g_done = 0u; }
}

// ---------------- kernel 2: fp16 mma Gram, one 128x128 tile per CTA ----------
// grid (33, 64): bi = blockIdx.y, bj = (bi + d) % 64, d = blockIdx.x.
// Upper-triangle coverage; d==32 duplicates for bi>=32 are skipped.
// 4-buffer cp.async pipeline, prefetch before the wait.
// __launch_bounds__(256, 2): TWO CTAs per SM — the co-resident CTA fills the
// tensor pipe during this CTA's barrier/CP_WAIT stalls (caps regs at 128).
__global__ void __launch_bounds__(256, 2)
mine_kernel(const int* __restrict__ labels) {
    extern __shared__ __half dyn[];
    __shared__ u64 rowPos[128], rowNeg[128], colPos[128], colNeg[128];
    __shared__ int lblI[128], lblJ[128];

    const int d  = blockIdx.x;
    const int bi = blockIdx.y;
    if (d == 32 && bi >= 32) return;
    const int bj = (bi + d) & (NBANDS - 1);
    const int i0 = bi * MTILE;
    const int j0 = bj * NTILE;

    const int tid  = threadIdx.x;
    const int lane = tid & 31;
    const int wid  = tid >> 5;
    const int gid  = lane >> 2;     // 0..7
    const int tig  = lane & 3;      // 0..3
    const int wr   = wid >> 1;      // 0..3 (row band: wr*32)
    const int wc   = wid & 1;       // 0..1 (col band: wc*64)

    if (tid < 128) {
        lblI[tid] = labels[i0 + tid];
        lblJ[tid] = labels[j0 + tid];
        rowPos[tid] = KPOS_INIT; rowNeg[tid] = KNEG_INIT;
        colPos[tid] = KPOS_INIT; colNeg[tid] = KNEG_INIT;
    }
    __syncthreads();

    int myLbl[2][2];
    #pragma unroll
    for (int mi = 0; mi < 2; mi++)
        #pragma unroll
        for (int h = 0; h < 2; h++)
            myLbl[mi][h] = lblI[wr * 32 + mi * 16 + h * 8 + gid];

    const uint32_t sbase = smem_u32(dyn);
    uint32_t abuf[NBUF], bbuf[NBUF];
    #pragma unroll
    for (int s = 0; s < NBUF; s++) {
        abuf[s] = sbase + s * TILE_BYTES;
        bbuf[s] = sbase + (NBUF + s) * TILE_BYTES;
    }

    // per-thread cp.async offsets: 256 threads = 64 rows x 4 cols of 16B
    const int ldrow = tid >> 2;               // 0..63 (x2 iters -> 128 rows)
    const int ldc   = tid & 3;                // 0..3
    const uint32_t soff0 = (uint32_t)(ldrow * SMS + ldc * 8) * 2u;
    const uint32_t soff1 = (uint32_t)((ldrow + 64) * SMS + ldc * 8) * 2u;

    // ldmatrix lane address bases (in halves)
    const int lr = lane & 7;
    const int rowA = wr * 32 + ((lane >> 3) & 1) * 8 + lr;  // + mi*16
    const int kA   = (lane >> 4) * 8;                        // + kk*16
    const int nB   = wc * 64 + (lane >> 4) * 8 + lr;         // + ni2*16
    const int kB   = ((lane >> 3) & 1) * 8;                  // + kk*16

    float acc[2][8][4];
    #pragma unroll
    for (int mi = 0; mi < 2; mi++)
        #pragma unroll
        for (int ni = 0; ni < 8; ni++)
            #pragma unroll
            for (int q = 0; q < 4; q++) acc[mi][ni][q] = 0.0f;

    // ---- prologue: commit stages 0 and 1 ----
    #pragma unroll
    for (int s = 0; s < 2; s++) {
        const int k0 = s * BKH;
        cp16(abuf[s] + soff0, g_unith + (size_t)(i0 + ldrow) * DDIM + k0 + ldc * 8);
        cp16(bbuf[s] + soff0, g_unith + (size_t)(j0 + ldrow) * DDIM + k0 + ldc * 8);
        cp16(abuf[s] + soff1, g_unith + (size_t)(i0 + 64 + ldrow) * DDIM + k0 + ldc * 8);
        cp16(bbuf[s] + soff1, g_unith + (size_t)(j0 + 64 + ldrow) * DDIM + k0 + ldc * 8);
        CP_COMMIT();
    }

    for (int s = 0; s < NSTAGES; s++) {
        // prefetch stage s+2 BEFORE the wait: its buffer was last read in
        // stage s-2, and the barrier at top of stage s-1 fenced those reads.
        if (s + 2 < NSTAGES) {
            const int nb = (s + 2) & (NBUF - 1);
            const int k0 = (s + 2) * BKH;
            cp16(abuf[nb] + soff0, g_unith + (size_t)(i0 + ldrow) * DDIM + k0 + ldc * 8);
            cp16(bbuf[nb] + soff0, g_unith + (size_t)(j0 + ldrow) * DDIM + k0 + ldc * 8);
            cp16(abuf[nb] + soff1, g_unith + (size_t)(i0 + 64 + ldrow) * DDIM + k0 + ldc * 8);
            cp16(bbuf[nb] + soff1, g_unith + (size_t)(j0 + 64 + ldrow) * DDIM + k0 + ldc * 8);
        }
        CP_COMMIT();       // one group per stage (empty in tail) keeps counts aligned

        CP_WAIT(2);        // 3 groups pending max -> group s complete
        __syncthreads();   // publish stage s; fence reads of stage s-1

        const uint32_t abase = abuf[s & (NBUF - 1)];
        const uint32_t bbase = bbuf[s & (NBUF - 1)];
        #pragma unroll
        for (int kk = 0; kk < 2; kk++) {
            uint32_t a0[4], a1[4];
            ldm_x4(a0, abase + (uint32_t)((rowA)      * SMS + kA + kk * 16) * 2u);
            ldm_x4(a1, abase + (uint32_t)((rowA + 16) * SMS + kA + kk * 16) * 2u);
            #pragma unroll
            for (int ni2 = 0; ni2 < 4; ni2++) {
                uint32_t b[4];
                ldm_x4(b, bbase + (uint32_t)((nB + ni2 * 16) * SMS + kB + kk * 16) * 2u);
                mma_f16(acc[0][2 * ni2],     a0, b[0], b[1]);
                mma_f16(acc[0][2 * ni2 + 1], a0, b[2], b[3]);
                mma_f16(acc[1][2 * ni2],     a1, b[0], b[1]);
                mma_f16(acc[1][2 * ni2 + 1], a1, b[2], b[3]);
            }
        }
    }

    // ---- row-side selection (rows of band bi) ----
    #pragma unroll
    for (int mi = 0; mi < 2; mi++) {
        #pragma unroll
        for (int h = 0; h < 2; h++) {
            int r   = wr * 32 + mi * 16 + h * 8 + gid;
            int gi  = i0 + r;
            int lbl = myLbl[mi][h];
            u64 pk = KPOS_INIT, nk = KNEG_INIT;
            #pragma unroll
            for (int ni = 0; ni < 8; ni++) {
                #pragma unroll
                for (int u = 0; u < 2; u++) {
                    int jc = wc * 64 + ni * 8 + tig * 2 + u;
                    int j  = j0 + jc;
                    u64 od = (u64)ford(acc[mi][ni][h * 2 + u]) << 32;
                    if (lblJ[jc] == lbl) {
                        if (j != gi) {
                            u64 k = od | (uint32_t)j;
                            if (k < pk) pk = k;
                        }
                    } else {
                        u64 k = od | (uint32_t)(0xFFFFFFFFu - j);
                        if (k > nk) nk = k;
                    }
                }
            }
            #pragma unroll
            for (int off = 2; off; off >>= 1) {
                u64 opk = __shfl_down_sync(0xffffffffu, pk, off, 4);
                u64 onk = __shfl_down_sync(0xffffffffu, nk, off, 4);
                if (opk < pk) pk = opk;
                if (onk > nk) nk = onk;
            }
            if (tig == 0) {
                if (pk != KPOS_INIT) atomicMin(&rowPos[r], pk);
                if (nk != KNEG_INIT) atomicMax(&rowNeg[r], nk);
            }
        }
    }

    // ---- column-side selection (rows of band bj, via transpose) ----
    #pragma unroll
    for (int ni = 0; ni < 8; ni++) {
        #pragma unroll
        for (int u = 0; u < 2; u++) {
            int jc = wc * 64 + ni * 8 + tig * 2 + u;
            int gj = j0 + jc;
            int lj = lblJ[jc];
            u64 pk = KPOS_INIT, nk = KNEG_INIT;
            #pragma unroll
            for (int mi = 0; mi < 2; mi++) {
                #pragma unroll
                for (int h = 0; h < 2; h++) {
                    int gi = i0 + wr * 32 + mi * 16 + h * 8 + gid;
                    u64 od = (u64)ford(acc[mi][ni][h * 2 + u]) << 32;
                    if (myLbl[mi][h] == lj) {
                        if (gi != gj) {
                            u64 k = od | (uint32_t)gi;
                            if (k < pk) pk = k;
                        }
                    } else {
                        u64 k = od | (uint32_t)(0xFFFFFFFFu - gi);
                        if (k > nk) nk = k;
                    }
                }
            }
            #pragma unroll
            for (int off = 16; off >= 4; off >>= 1) {
                u64 opk = __shfl_down_sync(0xffffffffu, pk, off);
                u64 onk = __shfl_down_sync(0xffffffffu, nk, off);
                if (opk < pk) pk = opk;
                if (onk > nk) nk = onk;
            }
            if (gid == 0) {
                if (pk != KPOS_INIT) atomicMin(&colPos[jc], pk);
                if (nk != KNEG_INIT) atomicMax(&colNeg[jc], nk);
            }
        }
    }
    __syncthreads();

    // ---- flush both bands (min/max idempotent -> diagonal overlap is safe) ----
    if (tid < 128) {
        u64 rp = rowPos[tid], rn = rowNeg[tid];
        u64 cp = colPos[tid], cn = colNeg[tid];
        if (rp != KPOS_INIT) atomicMin(&g_posKey[i0 + tid], rp);
        if (rn != KNEG_INIT) atomicMax(&g_negKey[i0 + tid], rn);
        if (cp != KPOS_INIT) atomicMin(&g_posKey[j0 + tid], cp);
        if (cn != KNEG_INIT) atomicMax(&g_negKey[j0 + tid], cn);
    }
}

// ---------------- kernel 3: triplet loss (warp per row) + fused reduction ----
__global__ void triplet_kernel(const float* __restrict__ emb, float* __restrict__ out) {
    __shared__ u64 ssum;
    __shared__ unsigned int scnt;
    int tid  = threadIdx.x;
    int lane = tid & 31;
    int i    = blockIdx.x * 8 + (tid >> 5);     // row handled by this warp

    if (tid == 0) { ssum = 0ull; scnt = 0u; }
    __syncthreads();

    u64 pk = g_posKey[i];
    u64 nk = g_negKey[i];
    bool valid = (pk != KPOS_INIT) && (nk != KNEG_INIT);
    if (valid) {
        int pi = (int)(uint32_t)(pk & 0xFFFFFFFFull);
        int ni = (int)(0xFFFFFFFFu - (uint32_t)(nk & 0xFFFFFFFFull));
        const float4* A = (const float4*)(emb + (size_t)i  * DDIM);
        const float4* P = (const float4*)(emb + (size_t)pi * DDIM);
        const float4* N = (const float4*)(emb + (size_t)ni * DDIM);

        float sap = 0.0f, san = 0.0f;
        #pragma unroll
        for (int q = 0; q < 4; q++) {
            float4 av = A[lane + 32 * q];
            float4 pv = P[lane + 32 * q];
            float4 nv = N[lane + 32 * q];
            float dd;
            dd = av.x - pv.x + 1e-6f; sap += dd * dd;
            dd = av.y - pv.y + 1e-6f; sap += dd * dd;
            dd = av.z - pv.z + 1e-6f; sap += dd * dd;
            dd = av.w - pv.w + 1e-6f; sap += dd * dd;
            dd = av.x - nv.x + 1e-6f; san += dd * dd;
            dd = av.y - nv.y + 1e-6f; san += dd * dd;
            dd = av.z - nv.z + 1e-6f; san += dd * dd;
            dd = av.w - nv.w + 1e-6f; san += dd * dd;
        }
        #pragma unroll
        for (int o = 16; o; o >>= 1) {
            sap += __shfl_xor_sync(0xffffffffu, sap, o);
            san += __shfl_xor_sync(0xffffffffu, san, o);
        }
        if (lane == 0) {
            float loss = fmaxf(sqrtf(sap) - sqrtf(san) + 1.0f, 0.0f);  // margin=1
            u64 fx = (u64)__double2ll_rn((double)loss * 4294967296.0);
            atomicAdd(&ssum, fx);
            atomicAdd(&scnt, 1u);
        }
    }
    __syncthreads();

    if (tid == 0) {
        if (scnt) {
            atomicAdd(&g_sumFix, ssum);
            atomicAdd(&g_cnt, scnt);
        }
        __threadfence();
        unsigned int ticket = atomicAdd(&g_done, 1u);
        if (ticket == gridDim.x - 1) {
            double s = (double)g_sumFix / 4294967296.0;
            float  c = (float)g_cnt;
            out[0] = (float)(s / (double)fmaxf(c, 1.0f));
        }
    }
}

// ---------------- launch ----------------
extern "C" void kernel_launch(void* const* d_in, const int* in_sizes, int n_in,
                              void* d_out, int out_size) {
    const float* emb    = (const float*)d_in[0];
    const int*   labels = (const int*)d_in[1];
    float*       out    = (float*)d_out;

    cudaFuncSetAttribute(mine_kernel,
                         cudaFuncAttributeMaxDynamicSharedMemorySize, DYN_SMEM);

    normalize_kernel<<<NROWS / 8, 256>>>(emb);
    mine_kernel<<<dim3(33, NBANDS), 256, DYN_SMEM>>>(labels);
    triplet_kernel<<<NROWS / 8, 256>>>(emb, out);
}